// round 1
// baseline (speedup 1.0000x reference)
#include <cuda_runtime.h>
#include <math.h>

// Problem constants
#define Bn 8
#define Nn 1025
#define Cc 512
#define Hh 8
#define HD 64
#define Mrows (Bn*Nn)   // 8200

// Scratch (no cudaMalloc allowed): device globals
__device__ float g_q[(size_t)Bn*Hh*Nn*HD];     // (b,h,n,d)
__device__ float g_k[(size_t)Bn*Hh*Nn*HD];
__device__ float g_v[(size_t)Bn*Hh*Nn*HD];
__device__ float g_att[(size_t)Bn*Nn*Cc];      // (b,n,c) pre-projection
__device__ float g_tab[Hh*32*32];              // collapsed geometry bias table

// ---------------------------------------------------------------------------
// Bias table: bias[h,i,j] (i,j>=1) depends only on (|px_i-px_j|, |py_i-py_j|)
// since w=h=1+1/G are constant (dw=dh=0). 8x32x32 entries, double precision.
// ---------------------------------------------------------------------------
__global__ void tab_kernel(const float* __restrict__ wg_w,
                           const float* __restrict__ wg_b) {
    int idx = blockIdx.x * blockDim.x + threadIdx.x;
    if (idx >= Hh * 1024) return;
    int h  = idx >> 10;
    int a  = (idx >> 5) & 31;
    int bb = idx & 31;
    // |cx_i-cx_j|/w = (a/32)/(33/32) = a/33
    double dx = log(fmax((double)a / 33.0, 1e-3));
    double dy = log(fmax((double)bb / 33.0, 1e-3));
    const float* w = wg_w + h * 64;
    double val = (double)wg_b[h];
    #pragma unroll
    for (int d = 0; d < 8; d++) {
        double dm = pow(1000.0, -(double)d / 8.0);
        double ax = 100.0 * dx * dm;
        double ay = 100.0 * dy * dm;
        val += sin(ax) * (double)w[d]      + sin(ay) * (double)w[8 + d]
             + cos(ax) * (double)w[32 + d] + cos(ay) * (double)w[40 + d];
    }
    // sin(0)=0 terms (d 16..31) drop; cos(0)=1 terms (d 48..63) sum:
    #pragma unroll
    for (int d = 48; d < 64; d++) val += (double)w[d];
    val = fmax(val, 0.0);           // relu
    val = log(fmax(val, 1e-6));     // log(clip)
    g_tab[idx] = (float)val;
}

// ---------------------------------------------------------------------------
// QKV GEMM: C[m,n] = dot(x[m,:], qkv_w[n,:]), M=8200, K=512, N=1536
// Writes directly into (b,h,n,d)-layout Q/K/V buffers.
// 64x64x16 tiles, 256 threads, 4x4 per-thread micro-tile.
// ---------------------------------------------------------------------------
__global__ __launch_bounds__(256) void qkv_gemm(const float* __restrict__ A,
                                                const float* __restrict__ W) {
    __shared__ float As[16][65];
    __shared__ float Bs[16][65];
    int tid = threadIdx.x;
    int m0 = blockIdx.y * 64, n0 = blockIdx.x * 64;
    int tx = tid & 15, ty = tid >> 4;
    int lr = tid >> 2, lc = (tid & 3) * 4;
    float acc[4][4] = {};
    for (int k0 = 0; k0 < 512; k0 += 16) {
        float4 av = make_float4(0.f, 0.f, 0.f, 0.f);
        int gm = m0 + lr;
        if (gm < Mrows) av = *(const float4*)(A + (size_t)gm * 512 + k0 + lc);
        As[lc][lr] = av.x; As[lc+1][lr] = av.y; As[lc+2][lr] = av.z; As[lc+3][lr] = av.w;
        float4 bv = *(const float4*)(W + (size_t)(n0 + lr) * 512 + k0 + lc);
        Bs[lc][lr] = bv.x; Bs[lc+1][lr] = bv.y; Bs[lc+2][lr] = bv.z; Bs[lc+3][lr] = bv.w;
        __syncthreads();
        #pragma unroll
        for (int kk = 0; kk < 16; kk++) {
            float a[4], b[4];
            #pragma unroll
            for (int i = 0; i < 4; i++) { a[i] = As[kk][ty*4+i]; b[i] = Bs[kk][tx*4+i]; }
            #pragma unroll
            for (int i = 0; i < 4; i++)
                #pragma unroll
                for (int j = 0; j < 4; j++) acc[i][j] += a[i] * b[j];
        }
        __syncthreads();
    }
    #pragma unroll
    for (int i = 0; i < 4; i++) {
        int mm = m0 + ty * 4 + i;
        if (mm >= Mrows) continue;
        int b = mm / Nn, ii = mm - b * Nn;
        #pragma unroll
        for (int j = 0; j < 4; j++) {
            int n = n0 + tx * 4 + j;
            int slot = n >> 9, hh = (n >> 6) & 7, d = n & 63;
            float* dst = (slot == 0) ? g_q : ((slot == 1) ? g_k : g_v);
            dst[(((size_t)(b * 8 + hh)) * Nn + ii) * 64 + d] = acc[i][j];
        }
    }
}

// ---------------------------------------------------------------------------
// Fused flash attention, fp32. One thread = one query row (q & o in regs).
// K/V tiles (32x64) in shared; lane-uniform j/d => all LDS are broadcasts.
// Bias via 32x32 table lookup from smem.
// ---------------------------------------------------------------------------
__global__ __launch_bounds__(128) void attn_kernel() {
    __shared__ float4 ks4[32 * 16];
    __shared__ float4 vs4[32 * 16];
    __shared__ float  tab[1024];
    int tid = threadIdx.x;
    int bh  = blockIdx.y;          // b*8 + h
    int h   = bh & 7;
    int row = blockIdx.x * 128 + tid;
    for (int i = tid; i < 1024; i += 128) tab[i] = g_tab[h * 1024 + i];
    bool active = row < Nn;

    float qreg[64];
    float o[64];
    #pragma unroll
    for (int d = 0; d < 64; d++) o[d] = 0.f;
    if (active) {
        const float4* qp = (const float4*)(g_q + ((size_t)bh * Nn + row) * 64);
        #pragma unroll
        for (int d4 = 0; d4 < 16; d4++) {
            float4 t = qp[d4];
            qreg[4*d4] = t.x; qreg[4*d4+1] = t.y; qreg[4*d4+2] = t.z; qreg[4*d4+3] = t.w;
        }
    }
    int pxi = (row - 1) >> 5, pyi = (row - 1) & 31;
    float m = -1e30f, l = 0.f;

    for (int jt = 0; jt < Nn; jt += 32) {
        int jmax = min(32, Nn - jt);
        __syncthreads();
        const float4* kg = (const float4*)(g_k + ((size_t)bh * Nn + jt) * 64);
        const float4* vg = (const float4*)(g_v + ((size_t)bh * Nn + jt) * 64);
        #pragma unroll
        for (int i = 0; i < 4; i++) {
            int f = tid + i * 128;
            int jj = f >> 4;
            if (jt + jj < Nn) { ks4[f] = kg[f]; vs4[f] = vg[f]; }
        }
        __syncthreads();
        if (active) {
            float s[32];
            float tmax = -1e30f;
            #pragma unroll
            for (int jj = 0; jj < 32; jj++) {
                if (jj < jmax) {
                    float acc = 0.f;
                    #pragma unroll
                    for (int d4 = 0; d4 < 16; d4++) {
                        float4 kk = ks4[jj * 16 + d4];
                        acc += qreg[4*d4]   * kk.x;
                        acc += qreg[4*d4+1] * kk.y;
                        acc += qreg[4*d4+2] * kk.z;
                        acc += qreg[4*d4+3] * kk.w;
                    }
                    int j = jt + jj;
                    float bias = 0.f;
                    if (row > 0 && j > 0) {
                        int pxj = (j - 1) >> 5, pyj = (j - 1) & 31;
                        bias = tab[abs(pxi - pxj) * 32 + abs(pyi - pyj)];
                    }
                    s[jj] = acc * 0.125f + bias;
                    tmax = fmaxf(tmax, s[jj]);
                }
            }
            float newm = fmaxf(m, tmax);
            float corr = __expf(m - newm);
            l *= corr;
            #pragma unroll
            for (int d = 0; d < 64; d++) o[d] *= corr;
            m = newm;
            #pragma unroll
            for (int jj = 0; jj < 32; jj++) {
                if (jj < jmax) {
                    float p = __expf(s[jj] - m);
                    l += p;
                    #pragma unroll
                    for (int d4 = 0; d4 < 16; d4++) {
                        float4 vv = vs4[jj * 16 + d4];
                        o[4*d4]   += p * vv.x;
                        o[4*d4+1] += p * vv.y;
                        o[4*d4+2] += p * vv.z;
                        o[4*d4+3] += p * vv.w;
                    }
                }
            }
        }
    }
    if (active) {
        float inv = 1.f / l;
        int b = bh >> 3;
        float4* op = (float4*)(g_att + ((size_t)(b * Nn + row)) * Cc + h * 64);
        #pragma unroll
        for (int d4 = 0; d4 < 16; d4++) {
            float4 t;
            t.x = o[4*d4]   * inv;
            t.y = o[4*d4+1] * inv;
            t.z = o[4*d4+2] * inv;
            t.w = o[4*d4+3] * inv;
            op[d4] = t;
        }
    }
}

// ---------------------------------------------------------------------------
// Output projection: out[m,n] = dot(att[m,:], proj_w[n,:]) + proj_b[n]
// M=8200, K=512, N=512
// ---------------------------------------------------------------------------
__global__ __launch_bounds__(256) void proj_gemm(const float* __restrict__ W,
                                                 const float* __restrict__ bias,
                                                 float* __restrict__ out) {
    __shared__ float As[16][65];
    __shared__ float Bs[16][65];
    const float* A = g_att;
    int tid = threadIdx.x;
    int m0 = blockIdx.y * 64, n0 = blockIdx.x * 64;
    int tx = tid & 15, ty = tid >> 4;
    int lr = tid >> 2, lc = (tid & 3) * 4;
    float acc[4][4] = {};
    for (int k0 = 0; k0 < 512; k0 += 16) {
        float4 av = make_float4(0.f, 0.f, 0.f, 0.f);
        int gm = m0 + lr;
        if (gm < Mrows) av = *(const float4*)(A + (size_t)gm * 512 + k0 + lc);
        As[lc][lr] = av.x; As[lc+1][lr] = av.y; As[lc+2][lr] = av.z; As[lc+3][lr] = av.w;
        float4 bv = *(const float4*)(W + (size_t)(n0 + lr) * 512 + k0 + lc);
        Bs[lc][lr] = bv.x; Bs[lc+1][lr] = bv.y; Bs[lc+2][lr] = bv.z; Bs[lc+3][lr] = bv.w;
        __syncthreads();
        #pragma unroll
        for (int kk = 0; kk < 16; kk++) {
            float a[4], b[4];
            #pragma unroll
            for (int i = 0; i < 4; i++) { a[i] = As[kk][ty*4+i]; b[i] = Bs[kk][tx*4+i]; }
            #pragma unroll
            for (int i = 0; i < 4; i++)
                #pragma unroll
                for (int j = 0; j < 4; j++) acc[i][j] += a[i] * b[j];
        }
        __syncthreads();
    }
    #pragma unroll
    for (int i = 0; i < 4; i++) {
        int mm = m0 + ty * 4 + i;
        if (mm >= Mrows) continue;
        #pragma unroll
        for (int j = 0; j < 4; j++) {
            int n = n0 + tx * 4 + j;
            out[(size_t)mm * 512 + n] = acc[i][j] + bias[n];
        }
    }
}

// ---------------------------------------------------------------------------
extern "C" void kernel_launch(void* const* d_in, const int* in_sizes, int n_in,
                              void* d_out, int out_size) {
    const float* x      = (const float*)d_in[0];
    const float* qkv_w  = (const float*)d_in[1];
    const float* proj_w = (const float*)d_in[2];
    const float* proj_b = (const float*)d_in[3];
    const float* wg_w   = (const float*)d_in[4];
    const float* wg_b   = (const float*)d_in[5];
    float* out = (float*)d_out;

    tab_kernel<<<32, 256>>>(wg_w, wg_b);
    qkv_gemm<<<dim3(1536 / 64, (Mrows + 63) / 64), 256>>>(x, qkv_w);
    attn_kernel<<<dim3((Nn + 127) / 128, Bn * Hh), 128>>>();
    proj_gemm<<<dim3(512 / 64, (Mrows + 63) / 64), 256>>>(proj_w, proj_b, out);
}

// round 2
// speedup vs baseline: 1.0111x; 1.0111x over previous
#include <cuda_runtime.h>
#include <math.h>

// Problem constants
#define Bn 8
#define Nn 1025
#define Cc 512
#define Hh 8
#define HD 64
#define Mrows (Bn*Nn)   // 8200

// Scratch (no cudaMalloc allowed): device globals
__device__ float g_q[(size_t)Bn*Hh*Nn*HD];     // (b,h,n,d)
__device__ float g_k[(size_t)Bn*Hh*Nn*HD];
__device__ float g_v[(size_t)Bn*Hh*Nn*HD];
__device__ float g_att[(size_t)Bn*Nn*Cc];      // (b,n,c) pre-projection
__device__ float g_tab[Hh*32*32];              // collapsed geometry bias table

// ---------------------------------------------------------------------------
// Bias table: bias[h,i,j] (i,j>=1) depends only on (|px_i-px_j|, |py_i-py_j|)
// since w=h=1+1/G are constant (dw=dh=0). 8x32x32 entries, double precision.
// ---------------------------------------------------------------------------
__global__ void tab_kernel(const float* __restrict__ wg_w,
                           const float* __restrict__ wg_b) {
    int idx = blockIdx.x * blockDim.x + threadIdx.x;
    if (idx >= Hh * 1024) return;
    int h  = idx >> 10;
    int a  = (idx >> 5) & 31;
    int bb = idx & 31;
    // |cx_i-cx_j|/w = (a/32)/(33/32) = a/33
    double dx = log(fmax((double)a / 33.0, 1e-3));
    double dy = log(fmax((double)bb / 33.0, 1e-3));
    const float* w = wg_w + h * 64;
    double val = (double)wg_b[h];
    #pragma unroll
    for (int d = 0; d < 8; d++) {
        double dm = pow(1000.0, -(double)d / 8.0);
        double ax = 100.0 * dx * dm;
        double ay = 100.0 * dy * dm;
        val += sin(ax) * (double)w[d]      + sin(ay) * (double)w[8 + d]
             + cos(ax) * (double)w[32 + d] + cos(ay) * (double)w[40 + d];
    }
    // sin(0)=0 terms (d 16..31) drop; cos(0)=1 terms (d 48..63) sum:
    #pragma unroll
    for (int d = 48; d < 64; d++) val += (double)w[d];
    val = fmax(val, 0.0);           // relu
    val = log(fmax(val, 1e-6));     // log(clip)
    g_tab[idx] = (float)val;
}

// ---------------------------------------------------------------------------
// QKV GEMM: C[m,n] = dot(x[m,:], qkv_w[n,:]), M=8200, K=512, N=1536
// Writes directly into (b,h,n,d)-layout Q/K/V buffers.
// 64x64x16 tiles, 256 threads, 4x4 per-thread micro-tile.
// ---------------------------------------------------------------------------
__global__ __launch_bounds__(256) void qkv_gemm(const float* __restrict__ A,
                                                const float* __restrict__ W) {
    __shared__ float As[16][65];
    __shared__ float Bs[16][65];
    int tid = threadIdx.x;
    int m0 = blockIdx.y * 64, n0 = blockIdx.x * 64;
    int tx = tid & 15, ty = tid >> 4;
    int lr = tid >> 2, lc = (tid & 3) * 4;
    float acc[4][4] = {};
    for (int k0 = 0; k0 < 512; k0 += 16) {
        float4 av = make_float4(0.f, 0.f, 0.f, 0.f);
        int gm = m0 + lr;
        if (gm < Mrows) av = *(const float4*)(A + (size_t)gm * 512 + k0 + lc);
        As[lc][lr] = av.x; As[lc+1][lr] = av.y; As[lc+2][lr] = av.z; As[lc+3][lr] = av.w;
        float4 bv = *(const float4*)(W + (size_t)(n0 + lr) * 512 + k0 + lc);
        Bs[lc][lr] = bv.x; Bs[lc+1][lr] = bv.y; Bs[lc+2][lr] = bv.z; Bs[lc+3][lr] = bv.w;
        __syncthreads();
        #pragma unroll
        for (int kk = 0; kk < 16; kk++) {
            float a[4], b[4];
            #pragma unroll
            for (int i = 0; i < 4; i++) { a[i] = As[kk][ty*4+i]; b[i] = Bs[kk][tx*4+i]; }
            #pragma unroll
            for (int i = 0; i < 4; i++)
                #pragma unroll
                for (int j = 0; j < 4; j++) acc[i][j] += a[i] * b[j];
        }
        __syncthreads();
    }
    #pragma unroll
    for (int i = 0; i < 4; i++) {
        int mm = m0 + ty * 4 + i;
        if (mm >= Mrows) continue;
        int b = mm / Nn, ii = mm - b * Nn;
        #pragma unroll
        for (int j = 0; j < 4; j++) {
            int n = n0 + tx * 4 + j;
            int slot = n >> 9, hh = (n >> 6) & 7, d = n & 63;
            float* dst = (slot == 0) ? g_q : ((slot == 1) ? g_k : g_v);
            dst[(((size_t)(b * 8 + hh)) * Nn + ii) * 64 + d] = acc[i][j];
        }
    }
}

// ---------------------------------------------------------------------------
// Fused flash attention, fp32. One thread = one query row (q & o in regs).
// K/V tiles (32x64) in shared; lane-uniform j/d => all LDS are broadcasts.
// Bias via 32x32 table lookup from smem.
// ---------------------------------------------------------------------------
__global__ __launch_bounds__(128) void attn_kernel() {
    __shared__ float4 ks4[32 * 16];
    __shared__ float4 vs4[32 * 16];
    __shared__ float  tab[1024];
    int tid = threadIdx.x;
    int bh  = blockIdx.y;          // b*8 + h
    int h   = bh & 7;
    int row = blockIdx.x * 128 + tid;
    for (int i = tid; i < 1024; i += 128) tab[i] = g_tab[h * 1024 + i];
    bool active = row < Nn;

    float qreg[64];
    float o[64];
    #pragma unroll
    for (int d = 0; d < 64; d++) o[d] = 0.f;
    if (active) {
        const float4* qp = (const float4*)(g_q + ((size_t)bh * Nn + row) * 64);
        #pragma unroll
        for (int d4 = 0; d4 < 16; d4++) {
            float4 t = qp[d4];
            qreg[4*d4] = t.x; qreg[4*d4+1] = t.y; qreg[4*d4+2] = t.z; qreg[4*d4+3] = t.w;
        }
    }
    int pxi = (row - 1) >> 5, pyi = (row - 1) & 31;
    float m = -1e30f, l = 0.f;

    for (int jt = 0; jt < Nn; jt += 32) {
        int jmax = min(32, Nn - jt);
        __syncthreads();
        const float4* kg = (const float4*)(g_k + ((size_t)bh * Nn + jt) * 64);
        const float4* vg = (const float4*)(g_v + ((size_t)bh * Nn + jt) * 64);
        #pragma unroll
        for (int i = 0; i < 4; i++) {
            int f = tid + i * 128;
            int jj = f >> 4;
            if (jt + jj < Nn) { ks4[f] = kg[f]; vs4[f] = vg[f]; }
        }
        __syncthreads();
        if (active) {
            float s[32];
            float tmax = -1e30f;
            #pragma unroll
            for (int jj = 0; jj < 32; jj++) {
                if (jj < jmax) {
                    float acc = 0.f;
                    #pragma unroll
                    for (int d4 = 0; d4 < 16; d4++) {
                        float4 kk = ks4[jj * 16 + d4];
                        acc += qreg[4*d4]   * kk.x;
                        acc += qreg[4*d4+1] * kk.y;
                        acc += qreg[4*d4+2] * kk.z;
                        acc += qreg[4*d4+3] * kk.w;
                    }
                    int j = jt + jj;
                    float bias = 0.f;
                    if (row > 0 && j > 0) {
                        int pxj = (j - 1) >> 5, pyj = (j - 1) & 31;
                        bias = tab[abs(pxi - pxj) * 32 + abs(pyi - pyj)];
                    }
                    s[jj] = acc * 0.125f + bias;
                    tmax = fmaxf(tmax, s[jj]);
                }
            }
            float newm = fmaxf(m, tmax);
            float corr = __expf(m - newm);
            l *= corr;
            #pragma unroll
            for (int d = 0; d < 64; d++) o[d] *= corr;
            m = newm;
            #pragma unroll
            for (int jj = 0; jj < 32; jj++) {
                if (jj < jmax) {
                    float p = __expf(s[jj] - m);
                    l += p;
                    #pragma unroll
                    for (int d4 = 0; d4 < 16; d4++) {
                        float4 vv = vs4[jj * 16 + d4];
                        o[4*d4]   += p * vv.x;
                        o[4*d4+1] += p * vv.y;
                        o[4*d4+2] += p * vv.z;
                        o[4*d4+3] += p * vv.w;
                    }
                }
            }
        }
    }
    if (active) {
        float inv = 1.f / l;
        int b = bh >> 3;
        float4* op = (float4*)(g_att + ((size_t)(b * Nn + row)) * Cc + h * 64);
        #pragma unroll
        for (int d4 = 0; d4 < 16; d4++) {
            float4 t;
            t.x = o[4*d4]   * inv;
            t.y = o[4*d4+1] * inv;
            t.z = o[4*d4+2] * inv;
            t.w = o[4*d4+3] * inv;
            op[d4] = t;
        }
    }
}

// ---------------------------------------------------------------------------
// Output projection: out[m,n] = dot(att[m,:], proj_w[n,:]) + proj_b[n]
// M=8200, K=512, N=512
// ---------------------------------------------------------------------------
__global__ __launch_bounds__(256) void proj_gemm(const float* __restrict__ W,
                                                 const float* __restrict__ bias,
                                                 float* __restrict__ out) {
    __shared__ float As[16][65];
    __shared__ float Bs[16][65];
    const float* A = g_att;
    int tid = threadIdx.x;
    int m0 = blockIdx.y * 64, n0 = blockIdx.x * 64;
    int tx = tid & 15, ty = tid >> 4;
    int lr = tid >> 2, lc = (tid & 3) * 4;
    float acc[4][4] = {};
    for (int k0 = 0; k0 < 512; k0 += 16) {
        float4 av = make_float4(0.f, 0.f, 0.f, 0.f);
        int gm = m0 + lr;
        if (gm < Mrows) av = *(const float4*)(A + (size_t)gm * 512 + k0 + lc);
        As[lc][lr] = av.x; As[lc+1][lr] = av.y; As[lc+2][lr] = av.z; As[lc+3][lr] = av.w;
        float4 bv = *(const float4*)(W + (size_t)(n0 + lr) * 512 + k0 + lc);
        Bs[lc][lr] = bv.x; Bs[lc+1][lr] = bv.y; Bs[lc+2][lr] = bv.z; Bs[lc+3][lr] = bv.w;
        __syncthreads();
        #pragma unroll
        for (int kk = 0; kk < 16; kk++) {
            float a[4], b[4];
            #pragma unroll
            for (int i = 0; i < 4; i++) { a[i] = As[kk][ty*4+i]; b[i] = Bs[kk][tx*4+i]; }
            #pragma unroll
            for (int i = 0; i < 4; i++)
                #pragma unroll
                for (int j = 0; j < 4; j++) acc[i][j] += a[i] * b[j];
        }
        __syncthreads();
    }
    #pragma unroll
    for (int i = 0; i < 4; i++) {
        int mm = m0 + ty * 4 + i;
        if (mm >= Mrows) continue;
        #pragma unroll
        for (int j = 0; j < 4; j++) {
            int n = n0 + tx * 4 + j;
            out[(size_t)mm * 512 + n] = acc[i][j] + bias[n];
        }
    }
}

// ---------------------------------------------------------------------------
extern "C" void kernel_launch(void* const* d_in, const int* in_sizes, int n_in,
                              void* d_out, int out_size) {
    const float* x      = (const float*)d_in[0];
    const float* qkv_w  = (const float*)d_in[1];
    const float* proj_w = (const float*)d_in[2];
    const float* proj_b = (const float*)d_in[3];
    const float* wg_w   = (const float*)d_in[4];
    const float* wg_b   = (const float*)d_in[5];
    float* out = (float*)d_out;

    tab_kernel<<<32, 256>>>(wg_w, wg_b);
    qkv_gemm<<<dim3(1536 / 64, (Mrows + 63) / 64), 256>>>(x, qkv_w);
    attn_kernel<<<dim3((Nn + 127) / 128, Bn * Hh), 128>>>();
    proj_gemm<<<dim3(512 / 64, (Mrows + 63) / 64), 256>>>(proj_w, proj_b, out);
}

// round 6
// speedup vs baseline: 2.6002x; 2.5718x over previous
#include <cuda_runtime.h>
#include <cuda_bf16.h>
#include <math.h>
#include <stdint.h>

// Problem constants
#define Bn 8
#define Nn 1025
#define Cc 512
#define Hh 8
#define HD 64
#define Mrows (Bn*Nn)   // 8200

// Scratch: device globals (no cudaMalloc allowed)
__device__ float g_q[(size_t)Bn*Hh*Nn*HD];     // (b,h,n,d)
__device__ float g_k[(size_t)Bn*Hh*Nn*HD];
__device__ float g_v[(size_t)Bn*Hh*Nn*HD];
__device__ float g_att[(size_t)Bn*Nn*Cc];      // (b,n,c) pre-projection
__device__ float g_tab[Hh*32*32];              // bias table, pre-scaled by log2(e)

// ==========================================================================
// Helpers: base-target tensor ops (mma.sync / ldmatrix — compile for sm_103)
// ==========================================================================
__device__ __forceinline__ uint32_t smem_u32(const void* p) {
    uint32_t a;
    asm("{ .reg .u64 t; cvta.to.shared.u64 t, %1; cvt.u32.u64 %0, t; }" : "=r"(a) : "l"(p));
    return a;
}
__device__ __forceinline__ void ldsm4(uint32_t* r, uint32_t a) {
    asm volatile("ldmatrix.sync.aligned.m8n8.x4.shared.b16 {%0,%1,%2,%3}, [%4];"
        : "=r"(r[0]), "=r"(r[1]), "=r"(r[2]), "=r"(r[3]) : "r"(a));
}
__device__ __forceinline__ void ldsm4t(uint32_t* r, uint32_t a) {
    asm volatile("ldmatrix.sync.aligned.m8n8.x4.trans.shared.b16 {%0,%1,%2,%3}, [%4];"
        : "=r"(r[0]), "=r"(r[1]), "=r"(r[2]), "=r"(r[3]) : "r"(a));
}
__device__ __forceinline__ void mma_bf16(float* c, const uint32_t* a, const uint32_t* b) {
    asm volatile("mma.sync.aligned.m16n8k16.row.col.f32.bf16.bf16.f32 "
        "{%0,%1,%2,%3}, {%4,%5,%6,%7}, {%8,%9}, {%0,%1,%2,%3};"
        : "+f"(c[0]), "+f"(c[1]), "+f"(c[2]), "+f"(c[3])
        : "r"(a[0]), "r"(a[1]), "r"(a[2]), "r"(a[3]), "r"(b[0]), "r"(b[1]));
}
__device__ __forceinline__ float ex2f(float x) {
    float y; asm("ex2.approx.f32 %0, %1;" : "=f"(y) : "f"(x)); return y;
}
__device__ __forceinline__ uint32_t pack_hi2(float a, float b, float& ra, float& rb) {
    __nv_bfloat16 ha = __float2bfloat16_rn(a);
    __nv_bfloat16 hb = __float2bfloat16_rn(b);
    ra = a - __bfloat162float(ha);
    rb = b - __bfloat162float(hb);
    __nv_bfloat162 p(ha, hb);
    return *reinterpret_cast<uint32_t*>(&p);
}
__device__ __forceinline__ uint32_t pack2(float a, float b) {
    __nv_bfloat162 p(__float2bfloat16_rn(a), __float2bfloat16_rn(b));
    return *reinterpret_cast<uint32_t*>(&p);
}

// ==========================================================================
// Bias table (collapsed geometry): stored pre-multiplied by log2(e)
// ==========================================================================
__global__ void tab_kernel(const float* __restrict__ wg_w,
                           const float* __restrict__ wg_b) {
    int idx = blockIdx.x * blockDim.x + threadIdx.x;
    if (idx >= Hh * 1024) return;
    int h  = idx >> 10;
    int a  = (idx >> 5) & 31;
    int bb = idx & 31;
    double dx = log(fmax((double)a / 33.0, 1e-3));
    double dy = log(fmax((double)bb / 33.0, 1e-3));
    const float* w = wg_w + h * 64;
    double val = (double)wg_b[h];
    #pragma unroll
    for (int d = 0; d < 8; d++) {
        double dm = pow(1000.0, -(double)d / 8.0);
        double ax = 100.0 * dx * dm;
        double ay = 100.0 * dy * dm;
        val += sin(ax) * (double)w[d]      + sin(ay) * (double)w[8 + d]
             + cos(ax) * (double)w[32 + d] + cos(ay) * (double)w[40 + d];
    }
    #pragma unroll
    for (int d = 48; d < 64; d++) val += (double)w[d];
    val = fmax(val, 0.0);
    val = log(fmax(val, 1e-6));
    g_tab[idx] = (float)(val * 1.4426950408889634);   // * log2(e)
}

// ==========================================================================
// Tensor GEMM via mma.sync (bf16 hi/lo split, 3 MMAs per k16): C = A @ B^T
// A: M x 512 (fp32 row-major), B: N x 512 (fp32 row-major).
// Block 256 thr (8 warps: 4 m-sub x 2 n-sub), tile 128x128, BK=32, dbl-buf.
// mode 0: scatter into g_q/g_k/g_v    mode 1: A = g_att, out = C + bias
// ==========================================================================
#define GP  80                 // smem row pitch in BYTES (40 bf16)
#define GTB (128 * GP)         // one tile: 10240 B
#define G_SMEM (8 * GTB)       // 2 buffers x {Ahi,Alo,Bhi,Blo}

__global__ __launch_bounds__(256, 1) void gemm_tc(const float* __restrict__ Ain,
                                                  const float* __restrict__ Bw,
                                                  int mode,
                                                  float* __restrict__ out,
                                                  const float* __restrict__ bias) {
    extern __shared__ char sm[];
    const float* A = (mode == 1) ? (const float*)g_att : Ain;
    int tid = threadIdx.x, lane = tid & 31, wid = tid >> 5;
    int wm = wid & 3, wn = wid >> 2;
    int n0 = blockIdx.x * 128, m0 = blockIdx.y * 128;
    uint32_t sb = smem_u32(sm);

    float C[2][8][4] = {};

    auto load_blk = [&](int kb, int bf) {
        int k0 = kb * 32;
        char* base = sm + bf * 4 * GTB;
        #pragma unroll
        for (int i = 0; i < 4; i++) {
            int idx = tid + i * 256;          // 0..1023
            int r = idx >> 3, c = (idx & 7) * 4;
            float4 v = make_float4(0.f, 0.f, 0.f, 0.f);
            int m = m0 + r;
            if (m < Mrows) v = *(const float4*)(A + (size_t)m * 512 + k0 + c);
            float e0, e1, e2, e3;
            uint32_t h01 = pack_hi2(v.x, v.y, e0, e1);
            uint32_t h23 = pack_hi2(v.z, v.w, e2, e3);
            *(uint2*)(base + r * GP + c * 2)       = make_uint2(h01, h23);
            *(uint2*)(base + GTB + r * GP + c * 2) = make_uint2(pack2(e0, e1), pack2(e2, e3));
            float4 w = *(const float4*)(Bw + (size_t)(n0 + r) * 512 + k0 + c);
            h01 = pack_hi2(w.x, w.y, e0, e1);
            h23 = pack_hi2(w.z, w.w, e2, e3);
            *(uint2*)(base + 2 * GTB + r * GP + c * 2) = make_uint2(h01, h23);
            *(uint2*)(base + 3 * GTB + r * GP + c * 2) = make_uint2(pack2(e0, e1), pack2(e2, e3));
        }
    };

    load_blk(0, 0);
    __syncthreads();

    #pragma unroll 1
    for (int kb = 0; kb < 16; kb++) {
        if (kb + 1 < 16) load_blk(kb + 1, (kb + 1) & 1);
        uint32_t tb = sb + (kb & 1) * 4 * GTB;
        #pragma unroll
        for (int ks = 0; ks < 2; ks++) {
            uint32_t ah[2][4], al[2][4];
            #pragma unroll
            for (int am = 0; am < 2; am++) {
                int row = wm * 32 + am * 16 + (lane & 15);
                int col = ks * 16 + ((lane >> 4) << 3);
                ldsm4(ah[am], tb + row * GP + col * 2);
                ldsm4(al[am], tb + GTB + row * GP + col * 2);
            }
            #pragma unroll
            for (int bp = 0; bp < 4; bp++) {
                int rown = wn * 64 + bp * 16 + (lane & 7) + ((lane >> 4) << 3);
                int col  = ks * 16 + (((lane >> 3) & 1) << 3);
                uint32_t th[4], tl[4];
                ldsm4(th, tb + 2 * GTB + rown * GP + col * 2);
                ldsm4(tl, tb + 3 * GTB + rown * GP + col * 2);
                #pragma unroll
                for (int s = 0; s < 2; s++) {
                    int bn = bp * 2 + s;
                    #pragma unroll
                    for (int am = 0; am < 2; am++) {
                        mma_bf16(C[am][bn], ah[am], th + s * 2);
                        mma_bf16(C[am][bn], ah[am], tl + s * 2);
                        mma_bf16(C[am][bn], al[am], th + s * 2);
                    }
                }
            }
        }
        __syncthreads();
    }

    // Epilogue
    int nbase = n0 + wn * 64;
    if (mode == 0) {
        int slot = nbase >> 9, h = (nbase >> 6) & 7;
        float* dst = (slot == 0) ? g_q : (slot == 1) ? g_k : g_v;
        #pragma unroll
        for (int am = 0; am < 2; am++)
        #pragma unroll
        for (int rr = 0; rr < 2; rr++) {
            int m = m0 + wm * 32 + am * 16 + (lane >> 2) + rr * 8;
            if (m < Mrows) {
                int bidx = m / Nn, ii = m - bidx * Nn;
                float* rp = dst + (((size_t)(bidx * 8 + h)) * Nn + ii) * 64;
                #pragma unroll
                for (int bn = 0; bn < 8; bn++) {
                    int d = bn * 8 + (lane & 3) * 2;
                    *(float2*)(rp + d) = make_float2(C[am][bn][rr * 2], C[am][bn][rr * 2 + 1]);
                }
            }
        }
    } else {
        #pragma unroll
        for (int am = 0; am < 2; am++)
        #pragma unroll
        for (int rr = 0; rr < 2; rr++) {
            int m = m0 + wm * 32 + am * 16 + (lane >> 2) + rr * 8;
            if (m < Mrows) {
                float* rp = out + (size_t)m * 512 + nbase;
                #pragma unroll
                for (int bn = 0; bn < 8; bn++) {
                    int d = bn * 8 + (lane & 3) * 2;
                    *(float2*)(rp + d) = make_float2(C[am][bn][rr * 2] + bias[nbase + d],
                                                     C[am][bn][rr * 2 + 1] + bias[nbase + d + 1]);
                }
            }
        }
    }
}

// ==========================================================================
// Flash attention on mma.sync. Block = 256 thr (8 warps x 16 rows = 128 q rows).
// Key tiles of 64. S = Q@K^T (hi/lo split), softmax in exp2 domain,
// P (regs, A-frag layout) @ V (trans-ldmatrix, hi/lo split).
// ==========================================================================
#define AP    144                       // smem row pitch bytes (72 bf16)
#define A_TAB 0
#define A_KH  4096
#define A_KL  (4096 + 1 * 9216)
#define A_VH  (4096 + 2 * 9216)
#define A_VL  (4096 + 3 * 9216)
#define A_SMEM (4096 + 4 * 9216)        // 40960 B

__global__ __launch_bounds__(256, 1) void attn_tc() {
    extern __shared__ char sm[];
    uint32_t sb = smem_u32(sm);
    int tid = threadIdx.x, lane = tid & 31, wid = tid >> 5;
    int bh = blockIdx.y, h = bh & 7, b = bh >> 3;
    int rowbase0 = blockIdx.x * 128;
    float* tab = (float*)(sm + A_TAB);

    for (int i = tid; i < 1024; i += 256) tab[i] = g_tab[h * 1024 + i];

    // ---- stage Q (two 64-row passes through K buffers), load Q frags
    uint32_t qh[4][4], ql[4][4];
    #pragma unroll 1
    for (int p = 0; p < 2; p++) {
        __syncthreads();
        #pragma unroll
        for (int i = 0; i < 4; i++) {
            int idx = tid + i * 256;
            int r = idx >> 4, c = (idx & 15) * 4;
            int grow = rowbase0 + p * 64 + r;
            float4 v = make_float4(0.f, 0.f, 0.f, 0.f);
            if (grow < Nn) v = *(const float4*)(g_q + ((size_t)bh * Nn + grow) * 64 + c);
            float e0, e1, e2, e3;
            uint32_t h01 = pack_hi2(v.x, v.y, e0, e1);
            uint32_t h23 = pack_hi2(v.z, v.w, e2, e3);
            *(uint2*)(sm + A_KH + r * AP + c * 2) = make_uint2(h01, h23);
            *(uint2*)(sm + A_KL + r * AP + c * 2) = make_uint2(pack2(e0, e1), pack2(e2, e3));
        }
        __syncthreads();
        if ((wid >> 2) == p) {
            int rloc = (wid & 3) * 16 + (lane & 15);
            #pragma unroll
            for (int ks = 0; ks < 4; ks++) {
                int col = ks * 16 + ((lane >> 4) << 3);
                ldsm4(qh[ks], sb + A_KH + rloc * AP + col * 2);
                ldsm4(ql[ks], sb + A_KL + rloc * AP + col * 2);
            }
        }
    }

    float O[8][4] = {};
    float mr0 = -1e30f, mr1 = -1e30f, lr0 = 0.f, lr1 = 0.f;
    int r0g = rowbase0 + wid * 16 + (lane >> 2);
    int r1g = r0g + 8;
    int ri0 = min(r0g, Nn - 1), ri1 = min(r1g, Nn - 1);
    int pxi0 = (ri0 - 1) >> 5, pyi0 = (ri0 - 1) & 31;
    int pxi1 = (ri1 - 1) >> 5, pyi1 = (ri1 - 1) & 31;
    const float c1 = 0.18033688011112042f;   // 0.125 * log2(e)

    #pragma unroll 1
    for (int jt = 0; jt < Nn; jt += 64) {
        __syncthreads();
        // stage K/V tile (hi/lo bf16)
        #pragma unroll
        for (int i = 0; i < 4; i++) {
            int idx = tid + i * 256;
            int r = idx >> 4, c = (idx & 15) * 4;
            int j = jt + r;
            float4 kv = make_float4(0.f, 0.f, 0.f, 0.f);
            float4 vv = make_float4(0.f, 0.f, 0.f, 0.f);
            if (j < Nn) {
                kv = *(const float4*)(g_k + ((size_t)bh * Nn + j) * 64 + c);
                vv = *(const float4*)(g_v + ((size_t)bh * Nn + j) * 64 + c);
            }
            float e0, e1, e2, e3;
            uint32_t h01 = pack_hi2(kv.x, kv.y, e0, e1);
            uint32_t h23 = pack_hi2(kv.z, kv.w, e2, e3);
            *(uint2*)(sm + A_KH + r * AP + c * 2) = make_uint2(h01, h23);
            *(uint2*)(sm + A_KL + r * AP + c * 2) = make_uint2(pack2(e0, e1), pack2(e2, e3));
            h01 = pack_hi2(vv.x, vv.y, e0, e1);
            h23 = pack_hi2(vv.z, vv.w, e2, e3);
            *(uint2*)(sm + A_VH + r * AP + c * 2) = make_uint2(h01, h23);
            *(uint2*)(sm + A_VL + r * AP + c * 2) = make_uint2(pack2(e0, e1), pack2(e2, e3));
        }
        __syncthreads();

        // ---- scores S = Q @ K^T (3-term split)
        float S[8][4] = {};
        #pragma unroll
        for (int ks = 0; ks < 4; ks++) {
            #pragma unroll
            for (int bp = 0; bp < 4; bp++) {
                int rown = bp * 16 + (lane & 7) + ((lane >> 4) << 3);
                int col  = ks * 16 + (((lane >> 3) & 1) << 3);
                uint32_t th[4], tl[4];
                ldsm4(th, sb + A_KH + rown * AP + col * 2);
                ldsm4(tl, sb + A_KL + rown * AP + col * 2);
                #pragma unroll
                for (int s = 0; s < 2; s++) {
                    mma_bf16(S[bp * 2 + s], qh[ks], th + s * 2);
                    mma_bf16(S[bp * 2 + s], qh[ks], tl + s * 2);
                    mma_bf16(S[bp * 2 + s], ql[ks], th + s * 2);
                }
            }
        }

        // ---- bias + mask + online softmax (exp2 domain)
        float mx0 = -1e30f, mx1 = -1e30f;
        #pragma unroll
        for (int bn = 0; bn < 8; bn++) {
            #pragma unroll
            for (int v = 0; v < 4; v++) {
                int j = jt + bn * 8 + (lane & 3) * 2 + (v & 1);
                float y;
                if (j >= Nn) {
                    y = -1e30f;
                } else {
                    int ri  = (v < 2) ? ri0 : ri1;
                    float bias = 0.f;
                    if (j > 0 && ri > 0) {
                        int pxj = (j - 1) >> 5, pyj = (j - 1) & 31;
                        int ax = ((v < 2) ? pxi0 : pxi1) - pxj; ax = ax < 0 ? -ax : ax;
                        int ay = ((v < 2) ? pyi0 : pyi1) - pyj; ay = ay < 0 ? -ay : ay;
                        bias = tab[ax * 32 + ay];
                    }
                    y = S[bn][v] * c1 + bias;
                }
                S[bn][v] = y;
                if (v < 2) mx0 = fmaxf(mx0, y); else mx1 = fmaxf(mx1, y);
            }
        }
        mx0 = fmaxf(mx0, __shfl_xor_sync(0xffffffffu, mx0, 1));
        mx0 = fmaxf(mx0, __shfl_xor_sync(0xffffffffu, mx0, 2));
        mx1 = fmaxf(mx1, __shfl_xor_sync(0xffffffffu, mx1, 1));
        mx1 = fmaxf(mx1, __shfl_xor_sync(0xffffffffu, mx1, 2));
        float nm0 = fmaxf(mr0, mx0), nm1 = fmaxf(mr1, mx1);
        float sc0 = ex2f(mr0 - nm0), sc1 = ex2f(mr1 - nm1);
        mr0 = nm0; mr1 = nm1;
        lr0 *= sc0; lr1 *= sc1;
        #pragma unroll
        for (int bn = 0; bn < 8; bn++) {
            O[bn][0] *= sc0; O[bn][1] *= sc0;
            O[bn][2] *= sc1; O[bn][3] *= sc1;
        }
        #pragma unroll
        for (int bn = 0; bn < 8; bn++) {
            float p0 = ex2f(S[bn][0] - mr0); lr0 += p0; S[bn][0] = p0;
            float p1 = ex2f(S[bn][1] - mr0); lr0 += p1; S[bn][1] = p1;
            float p2 = ex2f(S[bn][2] - mr1); lr1 += p2; S[bn][2] = p2;
            float p3 = ex2f(S[bn][3] - mr1); lr1 += p3; S[bn][3] = p3;
        }

        // ---- O += P @ V (P in regs as A-frags, V via trans-ldmatrix, split)
        #pragma unroll
        for (int t = 0; t < 4; t++) {
            uint32_t aph[4], apl[4];
            float e0, e1, e2, e3;
            aph[0] = pack_hi2(S[2 * t][0], S[2 * t][1], e0, e1);
            aph[1] = pack_hi2(S[2 * t][2], S[2 * t][3], e2, e3);
            apl[0] = pack2(e0, e1); apl[1] = pack2(e2, e3);
            aph[2] = pack_hi2(S[2 * t + 1][0], S[2 * t + 1][1], e0, e1);
            aph[3] = pack_hi2(S[2 * t + 1][2], S[2 * t + 1][3], e2, e3);
            apl[2] = pack2(e0, e1); apl[3] = pack2(e2, e3);
            #pragma unroll
            for (int dp = 0; dp < 4; dp++) {
                int rowv = t * 16 + (lane & 7) + (((lane >> 3) & 1) << 3);
                int colv = dp * 16 + ((lane >> 4) << 3);
                uint32_t vh4[4], vl4[4];
                ldsm4t(vh4, sb + A_VH + rowv * AP + colv * 2);
                ldsm4t(vl4, sb + A_VL + rowv * AP + colv * 2);
                #pragma unroll
                for (int s = 0; s < 2; s++) {
                    mma_bf16(O[dp * 2 + s], aph, vh4 + s * 2);
                    mma_bf16(O[dp * 2 + s], aph, vl4 + s * 2);
                    mma_bf16(O[dp * 2 + s], apl, vh4 + s * 2);
                }
            }
        }
    }

    // ---- finalize
    lr0 += __shfl_xor_sync(0xffffffffu, lr0, 1);
    lr0 += __shfl_xor_sync(0xffffffffu, lr0, 2);
    lr1 += __shfl_xor_sync(0xffffffffu, lr1, 1);
    lr1 += __shfl_xor_sync(0xffffffffu, lr1, 2);
    float inv0 = 1.f / lr0, inv1 = 1.f / lr1;
    if (r0g < Nn) {
        float* rp = g_att + ((size_t)(b * Nn + r0g)) * 512 + h * 64;
        #pragma unroll
        for (int bn = 0; bn < 8; bn++) {
            int d = bn * 8 + (lane & 3) * 2;
            *(float2*)(rp + d) = make_float2(O[bn][0] * inv0, O[bn][1] * inv0);
        }
    }
    if (r1g < Nn) {
        float* rp = g_att + ((size_t)(b * Nn + r1g)) * 512 + h * 64;
        #pragma unroll
        for (int bn = 0; bn < 8; bn++) {
            int d = bn * 8 + (lane & 3) * 2;
            *(float2*)(rp + d) = make_float2(O[bn][2] * inv1, O[bn][3] * inv1);
        }
    }
}

// ==========================================================================
extern "C" void kernel_launch(void* const* d_in, const int* in_sizes, int n_in,
                              void* d_out, int out_size) {
    const float* x      = (const float*)d_in[0];
    const float* qkv_w  = (const float*)d_in[1];
    const float* proj_w = (const float*)d_in[2];
    const float* proj_b = (const float*)d_in[3];
    const float* wg_w   = (const float*)d_in[4];
    const float* wg_b   = (const float*)d_in[5];
    float* out = (float*)d_out;

    cudaFuncSetAttribute(gemm_tc, cudaFuncAttributeMaxDynamicSharedMemorySize, G_SMEM);
    cudaFuncSetAttribute(attn_tc, cudaFuncAttributeMaxDynamicSharedMemorySize, A_SMEM);

    tab_kernel<<<32, 256>>>(wg_w, wg_b);
    gemm_tc<<<dim3(1536 / 128, (Mrows + 127) / 128), 256, G_SMEM>>>(x, qkv_w, 0, nullptr, nullptr);
    attn_tc<<<dim3((Nn + 127) / 128, Bn * Hh), 256, A_SMEM>>>();
    gemm_tc<<<dim3(512 / 128, (Mrows + 127) / 128), 256, G_SMEM>>>(nullptr, proj_w, 1, out, proj_b);
}